// round 7
// baseline (speedup 1.0000x reference)
#include <cuda_runtime.h>
#include <cuda_bf16.h>
#include <cstdint>

// ===========================================================================
// ExtractNet fused MoE via mma.sync bf16 (hi/lo 3-term split), sm_103-safe.
// R5 resubmit (x2): 512 threads / 16 warps, warp tile 16 rows x 32 cols.
// 1 CTA = 128 rows. mma.sync.m16n8k16 bf16 + ldmatrix, XOR-swizzled tiles.
// ===========================================================================

#define NT 512
#define MT 128

// smem byte offsets
#define OFF_X    0u        // X: hi 65536 | lo 65536
#define OFF_SCR  131072u   // 64K scratch (W1 | H1+W2+W3, H2 over H1)
#define OFF_GATE 196608u   // 128 x 16 fp32 = 8192
#define SM_SIZE  204800u

// scratch sublayout
#define SCR_W1HI 0u
#define SCR_W1LO 32768u
#define SCR_H1HI 0u        // H1 (and later H2) hi 16K | lo 16K
#define SCR_H1LO 16384u
#define SCR_W2HI 32768u
#define SCR_W2LO 40960u
#define SCR_W3HI 49152u
#define SCR_W3LO 57344u

// ---- device scratch: pre-split, transposed, pre-swizzled weights ----
__device__ __align__(16) __nv_bfloat16 g_W1hi[12 * 64 * 256];
__device__ __align__(16) __nv_bfloat16 g_W1lo[12 * 64 * 256];
__device__ __align__(16) __nv_bfloat16 g_W23hi[12 * 2 * 64 * 64];
__device__ __align__(16) __nv_bfloat16 g_W23lo[12 * 2 * 64 * 64];

// ---------------------------------------------------------------------------
__device__ __forceinline__ uint32_t smem_u32(const void* p) {
    uint32_t a;
    asm("{ .reg .u64 t; cvta.to.shared.u64 t, %1; cvt.u32.u64 %0, t; }" : "=r"(a) : "l"(p));
    return a;
}
__device__ __forceinline__ void ldsm4(uint32_t& r0, uint32_t& r1, uint32_t& r2,
                                      uint32_t& r3, uint32_t a) {
    asm volatile("ldmatrix.sync.aligned.m8n8.x4.shared.b16 {%0,%1,%2,%3}, [%4];"
                 : "=r"(r0), "=r"(r1), "=r"(r2), "=r"(r3) : "r"(a));
}
__device__ __forceinline__ void mma16816(float* c, uint32_t a0, uint32_t a1,
                                         uint32_t a2, uint32_t a3,
                                         uint32_t b0, uint32_t b1) {
    asm volatile(
        "mma.sync.aligned.m16n8k16.row.col.f32.bf16.bf16.f32 "
        "{%0,%1,%2,%3}, {%4,%5,%6,%7}, {%8,%9}, {%0,%1,%2,%3};"
        : "+f"(c[0]), "+f"(c[1]), "+f"(c[2]), "+f"(c[3])
        : "r"(a0), "r"(a1), "r"(a2), "r"(a3), "r"(b0), "r"(b1));
}
__device__ __forceinline__ void split2(float a, float b, uint32_t& h, uint32_t& l) {
    __nv_bfloat16 ha = __float2bfloat16(a), hb = __float2bfloat16(b);
    __nv_bfloat16 la = __float2bfloat16(a - __bfloat162float(ha));
    __nv_bfloat16 lb = __float2bfloat16(b - __bfloat162float(hb));
    h = (uint32_t)__bfloat16_as_ushort(ha) | ((uint32_t)__bfloat16_as_ushort(hb) << 16);
    l = (uint32_t)__bfloat16_as_ushort(la) | ((uint32_t)__bfloat16_as_ushort(lb) << 16);
}
// swizzled byte offsets (conflict-free ldmatrix)
__device__ __forceinline__ uint32_t xoff(int m, int k) {   // row stride 512B
    return (uint32_t)(m * 512 + ((((k >> 3) ^ (m & 7)) << 4) | ((k & 7) << 1)));
}
__device__ __forceinline__ uint32_t hoff(int m, int k) {   // row stride 128B
    return (uint32_t)(m * 128 + ((((k >> 3) ^ (m & 7)) << 4) | ((k & 7) << 1)));
}

// Warp GEMM: acc[4][4] += A[16m x 16*KS k] * B^T[32n x 16*KS k], 3-term split.
// aHi/aLo include the warp's A row offset; bHi/bLo include lrow + col-half offset.
template <int KS, int BST>
__device__ __forceinline__ void gemm_warp(uint32_t aHi, uint32_t aLo,
                                          uint32_t bHi, uint32_t bLo,
                                          int row7, int khalf, float (*acc)[4]) {
    #pragma unroll
    for (int ks = 0; ks < KS; ks++) {
        uint32_t u = (uint32_t)(((2 * ks + khalf) ^ row7) << 4);
        uint32_t ah0, ah1, ah2, ah3, al0, al1, al2, al3;
        ldsm4(ah0, ah1, ah2, ah3, aHi + u);
        ldsm4(al0, al1, al2, al3, aLo + u);
        #pragma unroll
        for (int p = 0; p < 2; p++) {
            uint32_t ub = (uint32_t)(p * 16 * BST) + u;
            uint32_t bh0, bh1, bh2, bh3, bl0, bl1, bl2, bl3;
            ldsm4(bh0, bh1, bh2, bh3, bHi + ub);
            ldsm4(bl0, bl1, bl2, bl3, bLo + ub);
            mma16816(acc[2 * p],     ah0, ah1, ah2, ah3, bh0, bh2);
            mma16816(acc[2 * p + 1], ah0, ah1, ah2, ah3, bh1, bh3);
            mma16816(acc[2 * p],     ah0, ah1, ah2, ah3, bl0, bl2);
            mma16816(acc[2 * p + 1], ah0, ah1, ah2, ah3, bl1, bl3);
            mma16816(acc[2 * p],     al0, al1, al2, al3, bh0, bh2);
            mma16816(acc[2 * p + 1], al0, al1, al2, al3, bh1, bh3);
        }
    }
}

// epilogue: bias + relu + split -> swizzled hidden tile (stride 128B)
__device__ __forceinline__ void epilogue(float (*acc)[4], const float* __restrict__ bias,
                                         char* S, uint32_t dHi, uint32_t dLo,
                                         int wr, int wc, int lane) {
    int g = lane >> 2, t4 = lane & 3;
    int m0 = wr * 16 + g, m1 = m0 + 8;
    #pragma unroll
    for (int nt = 0; nt < 4; nt++) {
        int col = wc * 32 + nt * 8 + t4 * 2;
        float bx = bias[col], by = bias[col + 1];
        float v00 = fmaxf(acc[nt][0] + bx, 0.f);
        float v01 = fmaxf(acc[nt][1] + by, 0.f);
        float v10 = fmaxf(acc[nt][2] + bx, 0.f);
        float v11 = fmaxf(acc[nt][3] + by, 0.f);
        uint32_t h0, l0, h1, l1;
        split2(v00, v01, h0, l0);
        split2(v10, v11, h1, l1);
        uint32_t o0 = hoff(m0, col), o1 = hoff(m1, col);
        *(uint32_t*)(S + dHi + o0) = h0;
        *(uint32_t*)(S + dLo + o0) = l0;
        *(uint32_t*)(S + dHi + o1) = h1;
        *(uint32_t*)(S + dLo + o1) = l1;
    }
}

// ===========================================================================
// prep kernel: split + transpose + swizzle weights into bf16 hi/lo scratch
// ===========================================================================
extern "C" __global__ void prep_w(const float* __restrict__ Wt1, const float* __restrict__ Wt2,
                                  const float* __restrict__ Wt3, const float* __restrict__ Ws1,
                                  const float* __restrict__ Ws2, const float* __restrict__ Ws3) {
    int idx = blockIdx.x * blockDim.x + threadIdx.x;
    const int N1 = 12 * 64 * 256;
    const int N2 = 12 * 2 * 64 * 64;
    if (idx < N1) {
        int e = idx >> 14, rem = idx & 16383;
        int n = rem >> 8, k = rem & 255;
        float v = (e < 8) ? Wt1[((size_t)e * 256 + k) * 64 + n]
                          : Ws1[((size_t)(e - 8) * 256 + k) * 64 + n];
        __nv_bfloat16 h = __float2bfloat16(v);
        __nv_bfloat16 l = __float2bfloat16(v - __bfloat162float(h));
        int d = e * 16384 + n * 256 + (((k >> 3) ^ (n & 7)) << 3) + (k & 7);
        g_W1hi[d] = h;
        g_W1lo[d] = l;
    } else if (idx < N1 + N2) {
        int j = idx - N1;
        int e = j >> 13, rem = j & 8191;
        int ly = rem >> 12, r = rem & 4095;
        int n = r >> 6, k = r & 63;
        float v;
        if (ly == 0) v = (e < 8) ? Wt2[((size_t)e * 64 + k) * 64 + n]
                                 : Ws2[((size_t)(e - 8) * 64 + k) * 64 + n];
        else         v = (e < 8) ? Wt3[((size_t)e * 64 + k) * 64 + n]
                                 : Ws3[((size_t)(e - 8) * 64 + k) * 64 + n];
        __nv_bfloat16 h = __float2bfloat16(v);
        __nv_bfloat16 l = __float2bfloat16(v - __bfloat162float(h));
        int d = (e * 2 + ly) * 4096 + n * 64 + (((k >> 3) ^ (n & 7)) << 3) + (k & 7);
        g_W23hi[d] = h;
        g_W23lo[d] = l;
    }
}

// ===========================================================================
// main kernel
// ===========================================================================
extern "C" __global__ void __launch_bounds__(NT, 1)
moe_mma(const float* __restrict__ X,
        const float* __restrict__ bt1, const float* __restrict__ bt2,
        const float* __restrict__ bt3, const float* __restrict__ bs1,
        const float* __restrict__ bs2, const float* __restrict__ bs3,
        const float* __restrict__ Wg,  const float* __restrict__ bg,
        float* __restrict__ Out)
{
    extern __shared__ __align__(16) char S[];
    const uint32_t SB = smem_u32(S);
    const int tid  = threadIdx.x;
    const int bm   = blockIdx.x * MT;
    const int w    = tid >> 5, lane = tid & 31;
    const int wr   = w >> 1, wc = w & 1;          // 8 row groups x 2 col halves
    const int lrow = lane & 15, khalf = lane >> 4;
    const int row7 = lrow & 7;
    float* sGate = (float*)(S + OFF_GATE);

    // ---- stage Wg into scratch ----
    #pragma unroll
    for (int i = 0; i < 2; i++)
        ((float4*)(S + OFF_SCR))[tid + i * NT] = ((const float4*)Wg)[tid + i * NT];
    __syncthreads();

    // ---- gates (exact fp32), threads 0..255: one per (row, task) ----
    if (tid < 256) {
        int m = tid >> 1, t = tid & 1;
        const float* wg = (const float*)(S + OFF_SCR) + t * 2048;
        const float* xr = X + (size_t)(bm + m) * 256;
        float lg[8];
        #pragma unroll
        for (int j = 0; j < 8; j++) lg[j] = bg[t * 8 + j];
        for (int k = 0; k < 256; k++) {
            float x = __ldg(xr + k);
            float4 w0 = *(const float4*)(wg + k * 8);
            float4 w1 = *(const float4*)(wg + k * 8 + 4);
            lg[0] += x * w0.x; lg[1] += x * w0.y; lg[2] += x * w0.z; lg[3] += x * w0.w;
            lg[4] += x * w1.x; lg[5] += x * w1.y; lg[6] += x * w1.z; lg[7] += x * w1.w;
        }
        float mx = lg[0];
        #pragma unroll
        for (int j = 1; j < 8; j++) mx = fmaxf(mx, lg[j]);
        float s = 0.f;
        #pragma unroll
        for (int j = 0; j < 8; j++) { lg[j] = __expf(lg[j] - mx); s += lg[j]; }
        float inv = 1.f / s;
        #pragma unroll
        for (int j = 0; j < 8; j++) sGate[m * 16 + t * 8 + j] = lg[j] * inv;
    }

    // ---- stage X: fp32 -> hi/lo bf16, swizzled [128][256] ----
    #pragma unroll
    for (int i = 0; i < 16; i++) {
        int q = tid + i * NT;             // 0..8191 float4 units
        int m = q >> 6, k = (q & 63) * 4;
        float4 x = *(const float4*)(X + (size_t)(bm + m) * 256 + k);
        uint32_t h0, l0, h1, l1;
        split2(x.x, x.y, h0, l0);
        split2(x.z, x.w, h1, l1);
        uint32_t o = xoff(m, k);
        *(uint2*)(S + OFF_X + o)          = make_uint2(h0, h1);
        *(uint2*)(S + OFF_X + 65536u + o) = make_uint2(l0, l1);
    }

    float tacc0[4][4], tacc1[4][4];
    #pragma unroll
    for (int nt = 0; nt < 4; nt++)
        #pragma unroll
        for (int j = 0; j < 4; j++) { tacc0[nt][j] = 0.f; tacc1[nt][j] = 0.f; }

    const uint32_t aX_hi = SB + OFF_X + (uint32_t)((wr * 16 + lrow) * 512);
    const uint32_t aX_lo = aX_hi + 65536u;
    const uint32_t aH_row = (uint32_t)((wr * 16 + lrow) * 128);
    const uint32_t bW1    = (uint32_t)((wc * 32 + lrow) * 512);
    const uint32_t bW23   = (uint32_t)((wc * 32 + lrow) * 128);

    for (int e = 0; e < 12; e++) {
        const float* b1p = (e < 8) ? bt1 + e * 64 : bs1 + (e - 8) * 64;
        const float* b2p = (e < 8) ? bt2 + e * 64 : bs2 + (e - 8) * 64;
        const float* b3p = (e < 8) ? bt3 + e * 64 : bs3 + (e - 8) * 64;

        float acc[4][4];

        // ---- stage W1 hi/lo (pre-swizzled raw copy, 64KB) ----
        __syncthreads();   // scratch free
        {
            const uint4* sH = (const uint4*)(g_W1hi + e * 16384);
            const uint4* sL = (const uint4*)(g_W1lo + e * 16384);
            #pragma unroll
            for (int i = 0; i < 4; i++) {
                int j = tid + i * NT;      // 0..2047
                ((uint4*)(S + OFF_SCR + SCR_W1HI))[j] = sH[j];
                ((uint4*)(S + OFF_SCR + SCR_W1LO))[j] = sL[j];
            }
        }
        __syncthreads();

        // ---- layer 1: [128,256] x [256,64] ----
        #pragma unroll
        for (int nt = 0; nt < 4; nt++)
            #pragma unroll
            for (int j = 0; j < 4; j++) acc[nt][j] = 0.f;
        gemm_warp<16, 512>(aX_hi, aX_lo,
                           SB + OFF_SCR + SCR_W1HI + bW1,
                           SB + OFF_SCR + SCR_W1LO + bW1,
                           row7, khalf, acc);
        __syncthreads();   // W1 reads done; H1/W2/W3 overwrite scratch

        // ---- epilogue 1 -> H1; stage W2 + W3 ----
        epilogue(acc, b1p, S, OFF_SCR + SCR_H1HI, OFF_SCR + SCR_H1LO, wr, wc, lane);
        {
            const uint4* s2H = (const uint4*)(g_W23hi + (e * 2 + 0) * 4096);
            const uint4* s2L = (const uint4*)(g_W23lo + (e * 2 + 0) * 4096);
            const uint4* s3H = (const uint4*)(g_W23hi + (e * 2 + 1) * 4096);
            const uint4* s3L = (const uint4*)(g_W23lo + (e * 2 + 1) * 4096);
            int j = tid;                    // 0..511 (512 uint4 per region)
            ((uint4*)(S + OFF_SCR + SCR_W2HI))[j] = s2H[j];
            ((uint4*)(S + OFF_SCR + SCR_W2LO))[j] = s2L[j];
            ((uint4*)(S + OFF_SCR + SCR_W3HI))[j] = s3H[j];
            ((uint4*)(S + OFF_SCR + SCR_W3LO))[j] = s3L[j];
        }
        __syncthreads();

        // ---- layer 2: [128,64] x [64,64] ----
        #pragma unroll
        for (int nt = 0; nt < 4; nt++)
            #pragma unroll
            for (int j = 0; j < 4; j++) acc[nt][j] = 0.f;
        gemm_warp<4, 128>(SB + OFF_SCR + SCR_H1HI + aH_row,
                          SB + OFF_SCR + SCR_H1LO + aH_row,
                          SB + OFF_SCR + SCR_W2HI + bW23,
                          SB + OFF_SCR + SCR_W2LO + bW23,
                          row7, khalf, acc);
        __syncthreads();   // H1 reads done; H2 overwrites H1 slot

        // ---- epilogue 2 -> H2 (over H1 slot) ----
        epilogue(acc, b2p, S, OFF_SCR + SCR_H1HI, OFF_SCR + SCR_H1LO, wr, wc, lane);
        __syncthreads();

        // ---- layer 3: [128,64] x [64,64] ----
        #pragma unroll
        for (int nt = 0; nt < 4; nt++)
            #pragma unroll
            for (int j = 0; j < 4; j++) acc[nt][j] = 0.f;
        gemm_warp<4, 128>(SB + OFF_SCR + SCR_H1HI + aH_row,
                          SB + OFF_SCR + SCR_H1LO + aH_row,
                          SB + OFF_SCR + SCR_W3HI + bW23,
                          SB + OFF_SCR + SCR_W3LO + bW23,
                          row7, khalf, acc);

        // ---- gated accumulation (next loop-top sync protects scratch) ----
        {
            int g = lane >> 2, t4 = lane & 3;
            int m0 = wr * 16 + g, m1 = m0 + 8;
            if (e < 8) {
                int t = e >> 2;
                float g0 = sGate[m0 * 16 + t * 8 + (e & 3)];
                float g1 = sGate[m1 * 16 + t * 8 + (e & 3)];
                float (*ta)[4] = t ? tacc1 : tacc0;
                #pragma unroll
                for (int nt = 0; nt < 4; nt++) {
                    int col = wc * 32 + nt * 8 + t4 * 2;
                    float bx = b3p[col], by = b3p[col + 1];
                    ta[nt][0] += g0 * (acc[nt][0] + bx);
                    ta[nt][1] += g0 * (acc[nt][1] + by);
                    ta[nt][2] += g1 * (acc[nt][2] + bx);
                    ta[nt][3] += g1 * (acc[nt][3] + by);
                }
            } else {
                int s = e - 8;
                float g00 = sGate[m0 * 16 + 4 + s],  g01 = sGate[m0 * 16 + 12 + s];
                float g10 = sGate[m1 * 16 + 4 + s],  g11 = sGate[m1 * 16 + 12 + s];
                #pragma unroll
                for (int nt = 0; nt < 4; nt++) {
                    int col = wc * 32 + nt * 8 + t4 * 2;
                    float bx = b3p[col], by = b3p[col + 1];
                    float v0 = acc[nt][0] + bx, v1 = acc[nt][1] + by;
                    float v2 = acc[nt][2] + bx, v3 = acc[nt][3] + by;
                    tacc0[nt][0] += g00 * v0; tacc0[nt][1] += g00 * v1;
                    tacc0[nt][2] += g10 * v2; tacc0[nt][3] += g10 * v3;
                    tacc1[nt][0] += g01 * v0; tacc1[nt][1] += g01 * v1;
                    tacc1[nt][2] += g11 * v2; tacc1[nt][3] += g11 * v3;
                }
            }
        }
    }

    // ---- writeback straight from registers (float2, quad-contiguous) ----
    {
        int g = lane >> 2, t4 = lane & 3;
        int m0 = bm + wr * 16 + g, m1 = m0 + 8;
        #pragma unroll
        for (int nt = 0; nt < 4; nt++) {
            int col = wc * 32 + nt * 8 + t4 * 2;
            *(float2*)(Out + (size_t)m0 * 128 + col)      = make_float2(tacc0[nt][0], tacc0[nt][1]);
            *(float2*)(Out + (size_t)m1 * 128 + col)      = make_float2(tacc0[nt][2], tacc0[nt][3]);
            *(float2*)(Out + (size_t)m0 * 128 + 64 + col) = make_float2(tacc1[nt][0], tacc1[nt][1]);
            *(float2*)(Out + (size_t)m1 * 128 + 64 + col) = make_float2(tacc1[nt][2], tacc1[nt][3]);
        }
    }
}

// ===========================================================================
extern "C" void kernel_launch(void* const* d_in, const int* in_sizes, int n_in,
                              void* d_out, int out_size) {
    const float* X   = (const float*)d_in[0];
    const float* Wt1 = (const float*)d_in[1];
    const float* bt1 = (const float*)d_in[2];
    const float* Wt2 = (const float*)d_in[3];
    const float* bt2 = (const float*)d_in[4];
    const float* Wt3 = (const float*)d_in[5];
    const float* bt3 = (const float*)d_in[6];
    const float* Ws1 = (const float*)d_in[7];
    const float* bs1 = (const float*)d_in[8];
    const float* Ws2 = (const float*)d_in[9];
    const float* bs2 = (const float*)d_in[10];
    const float* Ws3 = (const float*)d_in[11];
    const float* bs3 = (const float*)d_in[12];
    const float* Wg  = (const float*)d_in[13];
    const float* bg  = (const float*)d_in[14];
    float* Out = (float*)d_out;

    int B = in_sizes[0] / 256;
    int grid = B / MT;

    prep_w<<<1152, 256>>>(Wt1, Wt2, Wt3, Ws1, Ws2, Ws3);

    cudaFuncSetAttribute((const void*)moe_mma,
                         cudaFuncAttributeMaxDynamicSharedMemorySize, (int)SM_SIZE);
    moe_mma<<<grid, NT, SM_SIZE>>>(X, bt1, bt2, bt3, bs1, bs2, bs3, Wg, bg, Out);
}

// round 9
// speedup vs baseline: 1.1674x; 1.1674x over previous
#include <cuda_runtime.h>
#include <cuda_bf16.h>
#include <cstdint>

// ===========================================================================
// ExtractNet fused MoE via mma.sync bf16 (hi/lo 3-term split), sm_103-safe.
// R8 resubmit: MT=64, NT=256, smem 100KB -> 2 CTAs/SM so one CTA's GEMMs
// overlap the other CTA's barriers/epilogues/staging. Numerics = R4/R5.
// ===========================================================================

#define NT 256
#define MT 64

// smem byte offsets
#define OFF_X    0u        // X: hi 32768 | lo 32768
#define OFF_SCR  65536u    // 32K rotating scratch
#define OFF_GATE 98304u    // 64 x 16 fp32 = 4096
#define SM_SIZE  102400u

// scratch sublayout (rotating overlay)
#define SCR_W1HI 0u        // W1 K-chunk: hi 16K | lo 16K
#define SCR_W1LO 16384u
#define SCR_H1HI 0u        // H1: hi 8K | lo 8K
#define SCR_H1LO 8192u
#define SCR_W2HI 16384u    // W2: hi 8K | lo 8K
#define SCR_W2LO 24576u
#define SCR_H2HI 16384u    // H2 overwrites W2
#define SCR_H2LO 24576u
#define SCR_W3HI 0u        // W3 overwrites H1
#define SCR_W3LO 8192u

// ---- device scratch: pre-split, transposed, pre-swizzled weights ----
// g_W1: [e][kchunk(2)][n(64)][k(128)] swizzled rows of 256B
__device__ __align__(16) __nv_bfloat16 g_W1hi[12 * 2 * 64 * 128];
__device__ __align__(16) __nv_bfloat16 g_W1lo[12 * 2 * 64 * 128];
// g_W23: [e][layer(2)][n(64)][k(64)] swizzled rows of 128B
__device__ __align__(16) __nv_bfloat16 g_W23hi[12 * 2 * 64 * 64];
__device__ __align__(16) __nv_bfloat16 g_W23lo[12 * 2 * 64 * 64];

// ---------------------------------------------------------------------------
__device__ __forceinline__ uint32_t smem_u32(const void* p) {
    uint32_t a;
    asm("{ .reg .u64 t; cvta.to.shared.u64 t, %1; cvt.u32.u64 %0, t; }" : "=r"(a) : "l"(p));
    return a;
}
__device__ __forceinline__ void ldsm4(uint32_t& r0, uint32_t& r1, uint32_t& r2,
                                      uint32_t& r3, uint32_t a) {
    asm volatile("ldmatrix.sync.aligned.m8n8.x4.shared.b16 {%0,%1,%2,%3}, [%4];"
                 : "=r"(r0), "=r"(r1), "=r"(r2), "=r"(r3) : "r"(a));
}
__device__ __forceinline__ void mma16816(float* c, uint32_t a0, uint32_t a1,
                                         uint32_t a2, uint32_t a3,
                                         uint32_t b0, uint32_t b1) {
    asm volatile(
        "mma.sync.aligned.m16n8k16.row.col.f32.bf16.bf16.f32 "
        "{%0,%1,%2,%3}, {%4,%5,%6,%7}, {%8,%9}, {%0,%1,%2,%3};"
        : "+f"(c[0]), "+f"(c[1]), "+f"(c[2]), "+f"(c[3])
        : "r"(a0), "r"(a1), "r"(a2), "r"(a3), "r"(b0), "r"(b1));
}
__device__ __forceinline__ void split2(float a, float b, uint32_t& h, uint32_t& l) {
    __nv_bfloat16 ha = __float2bfloat16(a), hb = __float2bfloat16(b);
    __nv_bfloat16 la = __float2bfloat16(a - __bfloat162float(ha));
    __nv_bfloat16 lb = __float2bfloat16(b - __bfloat162float(hb));
    h = (uint32_t)__bfloat16_as_ushort(ha) | ((uint32_t)__bfloat16_as_ushort(hb) << 16);
    l = (uint32_t)__bfloat16_as_ushort(la) | ((uint32_t)__bfloat16_as_ushort(lb) << 16);
}
// swizzled byte offsets (conflict-free ldmatrix)
__device__ __forceinline__ uint32_t xoff(int m, int k) {   // row stride 512B
    return (uint32_t)(m * 512 + ((((k >> 3) ^ (m & 7)) << 4) | ((k & 7) << 1)));
}
__device__ __forceinline__ uint32_t hoff(int m, int k) {   // row stride 128B
    return (uint32_t)(m * 128 + ((((k >> 3) ^ (m & 7)) << 4) | ((k & 7) << 1)));
}

// Warp GEMM: acc[4][4] += A[16m x 16*KS k] * B^T[32n x 16*KS k], 3-term split.
template <int KS, int BST>
__device__ __forceinline__ void gemm_warp(uint32_t aHi, uint32_t aLo,
                                          uint32_t bHi, uint32_t bLo,
                                          int row7, int khalf, float (*acc)[4]) {
    #pragma unroll
    for (int ks = 0; ks < KS; ks++) {
        uint32_t u = (uint32_t)(((2 * ks + khalf) ^ row7) << 4);
        uint32_t ah0, ah1, ah2, ah3, al0, al1, al2, al3;
        ldsm4(ah0, ah1, ah2, ah3, aHi + u);
        ldsm4(al0, al1, al2, al3, aLo + u);
        #pragma unroll
        for (int p = 0; p < 2; p++) {
            uint32_t ub = (uint32_t)(p * 16 * BST) + u;
            uint32_t bh0, bh1, bh2, bh3, bl0, bl1, bl2, bl3;
            ldsm4(bh0, bh1, bh2, bh3, bHi + ub);
            ldsm4(bl0, bl1, bl2, bl3, bLo + ub);
            mma16816(acc[2 * p],     ah0, ah1, ah2, ah3, bh0, bh2);
            mma16816(acc[2 * p + 1], ah0, ah1, ah2, ah3, bh1, bh3);
            mma16816(acc[2 * p],     ah0, ah1, ah2, ah3, bl0, bl2);
            mma16816(acc[2 * p + 1], ah0, ah1, ah2, ah3, bl1, bl3);
            mma16816(acc[2 * p],     al0, al1, al2, al3, bh0, bh2);
            mma16816(acc[2 * p + 1], al0, al1, al2, al3, bh1, bh3);
        }
    }
}

// epilogue: bias + relu + split -> swizzled hidden tile (stride 128B)
__device__ __forceinline__ void epilogue(float (*acc)[4], const float* __restrict__ bias,
                                         char* S, uint32_t dHi, uint32_t dLo,
                                         int wr, int wc, int lane) {
    int g = lane >> 2, t4 = lane & 3;
    int m0 = wr * 16 + g, m1 = m0 + 8;
    #pragma unroll
    for (int nt = 0; nt < 4; nt++) {
        int col = wc * 32 + nt * 8 + t4 * 2;
        float bx = bias[col], by = bias[col + 1];
        float v00 = fmaxf(acc[nt][0] + bx, 0.f);
        float v01 = fmaxf(acc[nt][1] + by, 0.f);
        float v10 = fmaxf(acc[nt][2] + bx, 0.f);
        float v11 = fmaxf(acc[nt][3] + by, 0.f);
        uint32_t h0, l0, h1, l1;
        split2(v00, v01, h0, l0);
        split2(v10, v11, h1, l1);
        uint32_t o0 = hoff(m0, col), o1 = hoff(m1, col);
        *(uint32_t*)(S + dHi + o0) = h0;
        *(uint32_t*)(S + dLo + o0) = l0;
        *(uint32_t*)(S + dHi + o1) = h1;
        *(uint32_t*)(S + dLo + o1) = l1;
    }
}

// ===========================================================================
// prep kernel: split + transpose + swizzle weights into bf16 hi/lo scratch
// ===========================================================================
extern "C" __global__ void prep_w(const float* __restrict__ Wt1, const float* __restrict__ Wt2,
                                  const float* __restrict__ Wt3, const float* __restrict__ Ws1,
                                  const float* __restrict__ Ws2, const float* __restrict__ Ws3) {
    int idx = blockIdx.x * blockDim.x + threadIdx.x;
    const int N1 = 12 * 2 * 64 * 128;   // 196608
    const int N2 = 12 * 2 * 64 * 64;    // 98304
    if (idx < N1) {
        int e  = idx >> 14;            // 16384 per expert
        int rem = idx & 16383;
        int c  = rem >> 13;            // k-chunk
        int r2 = rem & 8191;
        int n  = r2 >> 7;
        int kl = r2 & 127;
        int kg = c * 128 + kl;
        float v = (e < 8) ? Wt1[((size_t)e * 256 + kg) * 64 + n]
                          : Ws1[((size_t)(e - 8) * 256 + kg) * 64 + n];
        __nv_bfloat16 h = __float2bfloat16(v);
        __nv_bfloat16 l = __float2bfloat16(v - __bfloat162float(h));
        int d = (e * 2 + c) * 8192 + n * 128 + (((kl >> 3) ^ (n & 7)) << 3) + (kl & 7);
        g_W1hi[d] = h;
        g_W1lo[d] = l;
    } else if (idx < N1 + N2) {
        int j = idx - N1;
        int e = j >> 13, rem = j & 8191;
        int ly = rem >> 12, r = rem & 4095;
        int n = r >> 6, k = r & 63;
        float v;
        if (ly == 0) v = (e < 8) ? Wt2[((size_t)e * 64 + k) * 64 + n]
                                 : Ws2[((size_t)(e - 8) * 64 + k) * 64 + n];
        else         v = (e < 8) ? Wt3[((size_t)e * 64 + k) * 64 + n]
                                 : Ws3[((size_t)(e - 8) * 64 + k) * 64 + n];
        __nv_bfloat16 h = __float2bfloat16(v);
        __nv_bfloat16 l = __float2bfloat16(v - __bfloat162float(h));
        int d = (e * 2 + ly) * 4096 + n * 64 + (((k >> 3) ^ (n & 7)) << 3) + (k & 7);
        g_W23hi[d] = h;
        g_W23lo[d] = l;
    }
}

// ===========================================================================
// main kernel: 64 rows/CTA, 8 warps (4 row groups x 2 col halves), 2 CTAs/SM
// ===========================================================================
extern "C" __global__ void __launch_bounds__(NT, 2)
moe_mma(const float* __restrict__ X,
        const float* __restrict__ bt1, const float* __restrict__ bt2,
        const float* __restrict__ bt3, const float* __restrict__ bs1,
        const float* __restrict__ bs2, const float* __restrict__ bs3,
        const float* __restrict__ Wg,  const float* __restrict__ bg,
        float* __restrict__ Out)
{
    extern __shared__ __align__(16) char S[];
    const uint32_t SB = smem_u32(S);
    const int tid  = threadIdx.x;
    const int bm   = blockIdx.x * MT;
    const int w    = tid >> 5, lane = tid & 31;
    const int wr   = w >> 1, wc = w & 1;          // 4 row groups x 2 col halves
    const int lrow = lane & 15, khalf = lane >> 4;
    const int row7 = lrow & 7;
    float* sGate = (float*)(S + OFF_GATE);

    // ---- stage Wg into scratch (16KB of the 32K scratch) ----
    #pragma unroll
    for (int i = 0; i < 4; i++)
        ((float4*)(S + OFF_SCR))[tid + i * NT] = ((const float4*)Wg)[tid + i * NT];
    __syncthreads();

    // ---- gates (exact fp32), threads 0..127: one per (row, task) ----
    if (tid < 128) {
        int m = tid >> 1, t = tid & 1;
        const float* wg = (const float*)(S + OFF_SCR) + t * 2048;
        const float* xr = X + (size_t)(bm + m) * 256;
        float lg[8];
        #pragma unroll
        for (int j = 0; j < 8; j++) lg[j] = bg[t * 8 + j];
        for (int k = 0; k < 256; k++) {
            float x = __ldg(xr + k);
            float4 w0 = *(const float4*)(wg + k * 8);
            float4 w1 = *(const float4*)(wg + k * 8 + 4);
            lg[0] += x * w0.x; lg[1] += x * w0.y; lg[2] += x * w0.z; lg[3] += x * w0.w;
            lg[4] += x * w1.x; lg[5] += x * w1.y; lg[6] += x * w1.z; lg[7] += x * w1.w;
        }
        float mx = lg[0];
        #pragma unroll
        for (int j = 1; j < 8; j++) mx = fmaxf(mx, lg[j]);
        float s = 0.f;
        #pragma unroll
        for (int j = 0; j < 8; j++) { lg[j] = __expf(lg[j] - mx); s += lg[j]; }
        float inv = 1.f / s;
        #pragma unroll
        for (int j = 0; j < 8; j++) sGate[m * 16 + t * 8 + j] = lg[j] * inv;
    }

    // ---- stage X: fp32 -> hi/lo bf16, swizzled [64][256] ----
    #pragma unroll
    for (int i = 0; i < 16; i++) {
        int q = tid + i * NT;             // 0..4095 float4 units
        int m = q >> 6, k = (q & 63) * 4;
        float4 x = *(const float4*)(X + (size_t)(bm + m) * 256 + k);
        uint32_t h0, l0, h1, l1;
        split2(x.x, x.y, h0, l0);
        split2(x.z, x.w, h1, l1);
        uint32_t o = xoff(m, k);
        *(uint2*)(S + OFF_X + o)          = make_uint2(h0, h1);
        *(uint2*)(S + OFF_X + 32768u + o) = make_uint2(l0, l1);
    }

    float tacc0[4][4], tacc1[4][4];
    #pragma unroll
    for (int nt = 0; nt < 4; nt++)
        #pragma unroll
        for (int j = 0; j < 4; j++) { tacc0[nt][j] = 0.f; tacc1[nt][j] = 0.f; }

    const uint32_t aX_hi  = SB + OFF_X + (uint32_t)((wr * 16 + lrow) * 512);
    const uint32_t aX_lo  = aX_hi + 32768u;
    const uint32_t aH_row = (uint32_t)((wr * 16 + lrow) * 128);
    const uint32_t bW1    = (uint32_t)((wc * 32 + lrow) * 256);
    const uint32_t bW23   = (uint32_t)((wc * 32 + lrow) * 128);

    for (int e = 0; e < 12; e++) {
        const float* b1p = (e < 8) ? bt1 + e * 64 : bs1 + (e - 8) * 64;
        const float* b2p = (e < 8) ? bt2 + e * 64 : bs2 + (e - 8) * 64;
        const float* b3p = (e < 8) ? bt3 + e * 64 : bs3 + (e - 8) * 64;

        float acc[4][4];
        #pragma unroll
        for (int nt = 0; nt < 4; nt++)
            #pragma unroll
            for (int j = 0; j < 4; j++) acc[nt][j] = 0.f;

        // ---- layer 1 in two 128-deep K chunks (32KB staging each) ----
        #pragma unroll
        for (int c = 0; c < 2; c++) {
            __syncthreads();   // scratch free (prev phase's reads done)
            {
                const uint4* sH = (const uint4*)(g_W1hi + (e * 2 + c) * 8192);
                const uint4* sL = (const uint4*)(g_W1lo + (e * 2 + c) * 8192);
                #pragma unroll
                for (int i = 0; i < 4; i++) {
                    int j = tid + i * NT;      // 0..1023 uint4
                    ((uint4*)(S + OFF_SCR + SCR_W1HI))[j] = sH[j];
                    ((uint4*)(S + OFF_SCR + SCR_W1LO))[j] = sL[j];
                }
            }
            __syncthreads();
            gemm_warp<8, 256>(aX_hi + c * 256u, aX_lo + c * 256u,
                              SB + OFF_SCR + SCR_W1HI + bW1,
                              SB + OFF_SCR + SCR_W1LO + bW1,
                              row7, khalf, acc);
        }
        __syncthreads();   // W1 reads done; H1 + W2 overwrite scratch

        // ---- epilogue 1 -> H1 [0,16K); stage W2 [16K,32K) ----
        epilogue(acc, b1p, S, OFF_SCR + SCR_H1HI, OFF_SCR + SCR_H1LO, wr, wc, lane);
        {
            const uint4* sH = (const uint4*)(g_W23hi + (e * 2 + 0) * 4096);
            const uint4* sL = (const uint4*)(g_W23lo + (e * 2 + 0) * 4096);
            #pragma unroll
            for (int i = 0; i < 2; i++) {
                int j = tid + i * NT;          // 0..511 uint4
                ((uint4*)(S + OFF_SCR + SCR_W2HI))[j] = sH[j];
                ((uint4*)(S + OFF_SCR + SCR_W2LO))[j] = sL[j];
            }
        }
        __syncthreads();

        // ---- layer 2: [64,64] x [64,64] ----
        #pragma unroll
        for (int nt = 0; nt < 4; nt++)
            #pragma unroll
            for (int j = 0; j < 4; j++) acc[nt][j] = 0.f;
        gemm_warp<4, 128>(SB + OFF_SCR + SCR_H1HI + aH_row,
                          SB + OFF_SCR + SCR_H1LO + aH_row,
                          SB + OFF_SCR + SCR_W2HI + bW23,
                          SB + OFF_SCR + SCR_W2LO + bW23,
                          row7, khalf, acc);
        __syncthreads();   // H1 + W2 reads done

        // ---- epilogue 2 -> H2 (over W2); stage W3 (over H1) ----
        epilogue(acc, b2p, S, OFF_SCR + SCR_H2HI, OFF_SCR + SCR_H2LO, wr, wc, lane);
        {
            const uint4* sH = (const uint4*)(g_W23hi + (e * 2 + 1) * 4096);
            const uint4* sL = (const uint4*)(g_W23lo + (e * 2 + 1) * 4096);
            #pragma unroll
            for (int i = 0; i < 2; i++) {
                int j = tid + i * NT;
                ((uint4*)(S + OFF_SCR + SCR_W3HI))[j] = sH[j];
                ((uint4*)(S + OFF_SCR + SCR_W3LO))[j] = sL[j];
            }
        }
        __syncthreads();

        // ---- layer 3: [64,64] x [64,64] ----
        #pragma unroll
        for (int nt = 0; nt < 4; nt++)
            #pragma unroll
            for (int j = 0; j < 4; j++) acc[nt][j] = 0.f;
        gemm_warp<4, 128>(SB + OFF_SCR + SCR_H2HI + aH_row,
                          SB + OFF_SCR + SCR_H2LO + aH_row,
                          SB + OFF_SCR + SCR_W3HI + bW23,
                          SB + OFF_SCR + SCR_W3LO + bW23,
                          row7, khalf, acc);

        // ---- gated accumulation (next loop-top sync protects scratch) ----
        {
            int g = lane >> 2, t4 = lane & 3;
            int m0 = wr * 16 + g, m1 = m0 + 8;
            if (e < 8) {
                int t = e >> 2;
                float g0 = sGate[m0 * 16 + t * 8 + (e & 3)];
                float g1 = sGate[m1 * 16 + t * 8 + (e & 3)];
                float (*ta)[4] = t ? tacc1 : tacc0;
                #pragma unroll
                for (int nt = 0; nt < 4; nt++) {
                    int col = wc * 32 + nt * 8 + t4 * 2;
                    float bx = b3p[col], by = b3p[col + 1];
                    ta[nt][0] += g0 * (acc[nt][0] + bx);
                    ta[nt][1] += g0 * (acc[nt][1] + by);
                    ta[nt][2] += g1 * (acc[nt][2] + bx);
                    ta[nt][3] += g1 * (acc[nt][3] + by);
                }
            } else {
                int s = e - 8;
                float g00 = sGate[m0 * 16 + 4 + s],  g01 = sGate[m0 * 16 + 12 + s];
                float g10 = sGate[m1 * 16 + 4 + s],  g11 = sGate[m1 * 16 + 12 + s];
                #pragma unroll
                for (int nt = 0; nt < 4; nt++) {
                    int col = wc * 32 + nt * 8 + t4 * 2;
                    float bx = b3p[col], by = b3p[col + 1];
                    float v0 = acc[nt][0] + bx, v1 = acc[nt][1] + by;
                    float v2 = acc[nt][2] + bx, v3 = acc[nt][3] + by;
                    tacc0[nt][0] += g00 * v0; tacc0[nt][1] += g00 * v1;
                    tacc0[nt][2] += g10 * v2; tacc0[nt][3] += g10 * v3;
                    tacc1[nt][0] += g01 * v0; tacc1[nt][1] += g01 * v1;
                    tacc1[nt][2] += g11 * v2; tacc1[nt][3] += g11 * v3;
                }
            }
        }
        __syncthreads();   // loop top: scratch free for next expert
    }

    // ---- writeback straight from registers (float2, quad-contiguous) ----
    {
        int g = lane >> 2, t4 = lane & 3;
        int m0 = bm + wr * 16 + g, m1 = m0 + 8;
        #pragma unroll
        for (int nt = 0; nt < 4; nt++) {
            int col = wc * 32 + nt * 8 + t4 * 2;
            *(float2*)(Out + (size_t)m0 * 128 + col)      = make_float2(tacc0[nt][0], tacc0[nt][1]);
            *(float2*)(Out + (size_t)m1 * 128 + col)      = make_float2(tacc0[nt][2], tacc0[nt][3]);
            *(float2*)(Out + (size_t)m0 * 128 + 64 + col) = make_float2(tacc1[nt][0], tacc1[nt][1]);
            *(float2*)(Out + (size_t)m1 * 128 + 64 + col) = make_float2(tacc1[nt][2], tacc1[nt][3]);
        }
    }
}

// ===========================================================================
extern "C" void kernel_launch(void* const* d_in, const int* in_sizes, int n_in,
                              void* d_out, int out_size) {
    const float* X   = (const float*)d_in[0];
    const float* Wt1 = (const float*)d_in[1];
    const float* bt1 = (const float*)d_in[2];
    const float* Wt2 = (const float*)d_in[3];
    const float* bt2 = (const float*)d_in[4];
    const float* Wt3 = (const float*)d_in[5];
    const float* bt3 = (const float*)d_in[6];
    const float* Ws1 = (const float*)d_in[7];
    const float* bs1 = (const float*)d_in[8];
    const float* Ws2 = (const float*)d_in[9];
    const float* bs2 = (const float*)d_in[10];
    const float* Ws3 = (const float*)d_in[11];
    const float* bs3 = (const float*)d_in[12];
    const float* Wg  = (const float*)d_in[13];
    const float* bg  = (const float*)d_in[14];
    float* Out = (float*)d_out;

    int B = in_sizes[0] / 256;
    int grid = B / MT;

    prep_w<<<1152, 256>>>(Wt1, Wt2, Wt3, Ws1, Ws2, Ws3);

    cudaFuncSetAttribute((const void*)moe_mma,
                         cudaFuncAttributeMaxDynamicSharedMemorySize, (int)SM_SIZE);
    moe_mma<<<grid, NT, SM_SIZE>>>(X, bt1, bt2, bt3, bs1, bs2, bs3, Wg, bg, Out);
}

// round 12
// speedup vs baseline: 1.1678x; 1.0004x over previous
#include <cuda_runtime.h>
#include <cuda_bf16.h>
#include <cstdint>

// ===========================================================================
// ExtractNet fused MoE via mma.sync bf16 (hi/lo 3-term split), sm_103-safe.
// R10 resubmit (x2): MT=64, NT=128, 4 warps of 32x32 tiles (0.33 LDSM/MMA),
// 2 CTAs/SM.
// ===========================================================================

#define NT 128
#define MT 64

// smem byte offsets
#define OFF_X    0u        // X: hi 32768 | lo 32768
#define OFF_SCR  65536u    // 32K rotating scratch
#define OFF_GATE 98304u    // 64 x 16 fp32 = 4096
#define SM_SIZE  102400u

// scratch sublayout (rotating overlay)
#define SCR_W1HI 0u        // W1 K-chunk: hi 16K | lo 16K
#define SCR_W1LO 16384u
#define SCR_H1HI 0u        // H1: hi 8K | lo 8K
#define SCR_H1LO 8192u
#define SCR_W2HI 16384u    // W2: hi 8K | lo 8K
#define SCR_W2LO 24576u
#define SCR_H2HI 16384u    // H2 overwrites W2
#define SCR_H2LO 24576u
#define SCR_W3HI 0u        // W3 overwrites H1
#define SCR_W3LO 8192u

// ---- device scratch: pre-split, transposed, pre-swizzled weights ----
__device__ __align__(16) __nv_bfloat16 g_W1hi[12 * 2 * 64 * 128];
__device__ __align__(16) __nv_bfloat16 g_W1lo[12 * 2 * 64 * 128];
__device__ __align__(16) __nv_bfloat16 g_W23hi[12 * 2 * 64 * 64];
__device__ __align__(16) __nv_bfloat16 g_W23lo[12 * 2 * 64 * 64];

// ---------------------------------------------------------------------------
__device__ __forceinline__ uint32_t smem_u32(const void* p) {
    uint32_t a;
    asm("{ .reg .u64 t; cvta.to.shared.u64 t, %1; cvt.u32.u64 %0, t; }" : "=r"(a) : "l"(p));
    return a;
}
__device__ __forceinline__ void ldsm4(uint32_t& r0, uint32_t& r1, uint32_t& r2,
                                      uint32_t& r3, uint32_t a) {
    asm volatile("ldmatrix.sync.aligned.m8n8.x4.shared.b16 {%0,%1,%2,%3}, [%4];"
                 : "=r"(r0), "=r"(r1), "=r"(r2), "=r"(r3) : "r"(a));
}
__device__ __forceinline__ void mma16816(float* c, uint32_t a0, uint32_t a1,
                                         uint32_t a2, uint32_t a3,
                                         uint32_t b0, uint32_t b1) {
    asm volatile(
        "mma.sync.aligned.m16n8k16.row.col.f32.bf16.bf16.f32 "
        "{%0,%1,%2,%3}, {%4,%5,%6,%7}, {%8,%9}, {%0,%1,%2,%3};"
        : "+f"(c[0]), "+f"(c[1]), "+f"(c[2]), "+f"(c[3])
        : "r"(a0), "r"(a1), "r"(a2), "r"(a3), "r"(b0), "r"(b1));
}
__device__ __forceinline__ void split2(float a, float b, uint32_t& h, uint32_t& l) {
    __nv_bfloat16 ha = __float2bfloat16(a), hb = __float2bfloat16(b);
    __nv_bfloat16 la = __float2bfloat16(a - __bfloat162float(ha));
    __nv_bfloat16 lb = __float2bfloat16(b - __bfloat162float(hb));
    h = (uint32_t)__bfloat16_as_ushort(ha) | ((uint32_t)__bfloat16_as_ushort(hb) << 16);
    l = (uint32_t)__bfloat16_as_ushort(la) | ((uint32_t)__bfloat16_as_ushort(lb) << 16);
}
// swizzled byte offsets (conflict-free ldmatrix)
__device__ __forceinline__ uint32_t xoff(int m, int k) {   // row stride 512B
    return (uint32_t)(m * 512 + ((((k >> 3) ^ (m & 7)) << 4) | ((k & 7) << 1)));
}
__device__ __forceinline__ uint32_t hoff(int m, int k) {   // row stride 128B
    return (uint32_t)(m * 128 + ((((k >> 3) ^ (m & 7)) << 4) | ((k & 7) << 1)));
}

// Warp GEMM 32x32: acc[2][4][4] += A[32m x 16*KS k] * B^T[32n x 16*KS k].
// 3-term split; per k-step: 4 A-LDSM + 4 B-LDSM feed 24 MMAs.
// AST: A row stride bytes. BST: B row stride bytes.
template <int KS, int AST, int BST>
__device__ __forceinline__ void gemm_warp(uint32_t aHi, uint32_t aLo,
                                          uint32_t bHi, uint32_t bLo,
                                          int row7, int khalf, float (*acc)[4][4]) {
    #pragma unroll
    for (int ks = 0; ks < KS; ks++) {
        uint32_t u = (uint32_t)(((2 * ks + khalf) ^ row7) << 4);
        // A fragments: two m16 groups, hi + lo
        uint32_t ah[2][4], al[2][4];
        ldsm4(ah[0][0], ah[0][1], ah[0][2], ah[0][3], aHi + u);
        ldsm4(ah[1][0], ah[1][1], ah[1][2], ah[1][3], aHi + 16u * AST + u);
        ldsm4(al[0][0], al[0][1], al[0][2], al[0][3], aLo + u);
        ldsm4(al[1][0], al[1][1], al[1][2], al[1][3], aLo + 16u * AST + u);
        #pragma unroll
        for (int p = 0; p < 2; p++) {
            uint32_t ub = (uint32_t)(p * 16 * BST) + u;
            uint32_t bh0, bh1, bh2, bh3, bl0, bl1, bl2, bl3;
            ldsm4(bh0, bh1, bh2, bh3, bHi + ub);
            ldsm4(bl0, bl1, bl2, bl3, bLo + ub);
            #pragma unroll
            for (int mm = 0; mm < 2; mm++) {
                mma16816(acc[mm][2 * p],     ah[mm][0], ah[mm][1], ah[mm][2], ah[mm][3], bh0, bh2);
                mma16816(acc[mm][2 * p + 1], ah[mm][0], ah[mm][1], ah[mm][2], ah[mm][3], bh1, bh3);
                mma16816(acc[mm][2 * p],     ah[mm][0], ah[mm][1], ah[mm][2], ah[mm][3], bl0, bl2);
                mma16816(acc[mm][2 * p + 1], ah[mm][0], ah[mm][1], ah[mm][2], ah[mm][3], bl1, bl3);
                mma16816(acc[mm][2 * p],     al[mm][0], al[mm][1], al[mm][2], al[mm][3], bh0, bh2);
                mma16816(acc[mm][2 * p + 1], al[mm][0], al[mm][1], al[mm][2], al[mm][3], bh1, bh3);
            }
        }
    }
}

// epilogue: bias + relu + split -> swizzled hidden tile (stride 128B)
__device__ __forceinline__ void epilogue(float (*acc)[4][4], const float* __restrict__ bias,
                                         char* S, uint32_t dHi, uint32_t dLo,
                                         int wr, int wc, int lane) {
    int g = lane >> 2, t4 = lane & 3;
    #pragma unroll
    for (int mm = 0; mm < 2; mm++) {
        int m0 = wr * 32 + mm * 16 + g, m1 = m0 + 8;
        #pragma unroll
        for (int nt = 0; nt < 4; nt++) {
            int col = wc * 32 + nt * 8 + t4 * 2;
            float bx = bias[col], by = bias[col + 1];
            float v00 = fmaxf(acc[mm][nt][0] + bx, 0.f);
            float v01 = fmaxf(acc[mm][nt][1] + by, 0.f);
            float v10 = fmaxf(acc[mm][nt][2] + bx, 0.f);
            float v11 = fmaxf(acc[mm][nt][3] + by, 0.f);
            uint32_t h0, l0, h1, l1;
            split2(v00, v01, h0, l0);
            split2(v10, v11, h1, l1);
            uint32_t o0 = hoff(m0, col), o1 = hoff(m1, col);
            *(uint32_t*)(S + dHi + o0) = h0;
            *(uint32_t*)(S + dLo + o0) = l0;
            *(uint32_t*)(S + dHi + o1) = h1;
            *(uint32_t*)(S + dLo + o1) = l1;
        }
    }
}

// ===========================================================================
// prep kernel: split + transpose + swizzle weights into bf16 hi/lo scratch
// ===========================================================================
extern "C" __global__ void prep_w(const float* __restrict__ Wt1, const float* __restrict__ Wt2,
                                  const float* __restrict__ Wt3, const float* __restrict__ Ws1,
                                  const float* __restrict__ Ws2, const float* __restrict__ Ws3) {
    int idx = blockIdx.x * blockDim.x + threadIdx.x;
    const int N1 = 12 * 2 * 64 * 128;
    const int N2 = 12 * 2 * 64 * 64;
    if (idx < N1) {
        int e  = idx >> 14;
        int rem = idx & 16383;
        int c  = rem >> 13;
        int r2 = rem & 8191;
        int n  = r2 >> 7;
        int kl = r2 & 127;
        int kg = c * 128 + kl;
        float v = (e < 8) ? Wt1[((size_t)e * 256 + kg) * 64 + n]
                          : Ws1[((size_t)(e - 8) * 256 + kg) * 64 + n];
        __nv_bfloat16 h = __float2bfloat16(v);
        __nv_bfloat16 l = __float2bfloat16(v - __bfloat162float(h));
        int d = (e * 2 + c) * 8192 + n * 128 + (((kl >> 3) ^ (n & 7)) << 3) + (kl & 7);
        g_W1hi[d] = h;
        g_W1lo[d] = l;
    } else if (idx < N1 + N2) {
        int j = idx - N1;
        int e = j >> 13, rem = j & 8191;
        int ly = rem >> 12, r = rem & 4095;
        int n = r >> 6, k = r & 63;
        float v;
        if (ly == 0) v = (e < 8) ? Wt2[((size_t)e * 64 + k) * 64 + n]
                                 : Ws2[((size_t)(e - 8) * 64 + k) * 64 + n];
        else         v = (e < 8) ? Wt3[((size_t)e * 64 + k) * 64 + n]
                                 : Ws3[((size_t)(e - 8) * 64 + k) * 64 + n];
        __nv_bfloat16 h = __float2bfloat16(v);
        __nv_bfloat16 l = __float2bfloat16(v - __bfloat162float(h));
        int d = (e * 2 + ly) * 4096 + n * 64 + (((k >> 3) ^ (n & 7)) << 3) + (k & 7);
        g_W23hi[d] = h;
        g_W23lo[d] = l;
    }
}

// ===========================================================================
// main kernel: 64 rows/CTA, 4 warps (2x2 grid of 32x32 tiles), 2 CTAs/SM
// ===========================================================================
extern "C" __global__ void __launch_bounds__(NT, 2)
moe_mma(const float* __restrict__ X,
        const float* __restrict__ bt1, const float* __restrict__ bt2,
        const float* __restrict__ bt3, const float* __restrict__ bs1,
        const float* __restrict__ bs2, const float* __restrict__ bs3,
        const float* __restrict__ Wg,  const float* __restrict__ bg,
        float* __restrict__ Out)
{
    extern __shared__ __align__(16) char S[];
    const uint32_t SB = smem_u32(S);
    const int tid  = threadIdx.x;
    const int bm   = blockIdx.x * MT;
    const int w    = tid >> 5, lane = tid & 31;
    const int wr   = w >> 1, wc = w & 1;          // 2 row groups x 2 col halves
    const int lrow = lane & 15, khalf = lane >> 4;
    const int row7 = lrow & 7;
    float* sGate = (float*)(S + OFF_GATE);

    // ---- stage Wg into scratch (16KB of the 32K scratch) ----
    #pragma unroll
    for (int i = 0; i < 8; i++)
        ((float4*)(S + OFF_SCR))[tid + i * NT] = ((const float4*)Wg)[tid + i * NT];
    __syncthreads();

    // ---- gates (exact fp32): all 128 threads, one per (row, task) ----
    {
        int m = tid >> 1, t = tid & 1;
        const float* wg = (const float*)(S + OFF_SCR) + t * 2048;
        const float* xr = X + (size_t)(bm + m) * 256;
        float lg[8];
        #pragma unroll
        for (int j = 0; j < 8; j++) lg[j] = bg[t * 8 + j];
        for (int k = 0; k < 256; k++) {
            float x = __ldg(xr + k);
            float4 w0 = *(const float4*)(wg + k * 8);
            float4 w1 = *(const float4*)(wg + k * 8 + 4);
            lg[0] += x * w0.x; lg[1] += x * w0.y; lg[2] += x * w0.z; lg[3] += x * w0.w;
            lg[4] += x * w1.x; lg[5] += x * w1.y; lg[6] += x * w1.z; lg[7] += x * w1.w;
        }
        float mx = lg[0];
        #pragma unroll
        for (int j = 1; j < 8; j++) mx = fmaxf(mx, lg[j]);
        float s = 0.f;
        #pragma unroll
        for (int j = 0; j < 8; j++) { lg[j] = __expf(lg[j] - mx); s += lg[j]; }
        float inv = 1.f / s;
        #pragma unroll
        for (int j = 0; j < 8; j++) sGate[m * 16 + t * 8 + j] = lg[j] * inv;
    }

    // ---- stage X: fp32 -> hi/lo bf16, swizzled [64][256] ----
    #pragma unroll
    for (int i = 0; i < 32; i++) {
        int q = tid + i * NT;             // 0..4095 float4 units
        int m = q >> 6, k = (q & 63) * 4;
        float4 x = *(const float4*)(X + (size_t)(bm + m) * 256 + k);
        uint32_t h0, l0, h1, l1;
        split2(x.x, x.y, h0, l0);
        split2(x.z, x.w, h1, l1);
        uint32_t o = xoff(m, k);
        *(uint2*)(S + OFF_X + o)          = make_uint2(h0, h1);
        *(uint2*)(S + OFF_X + 32768u + o) = make_uint2(l0, l1);
    }

    float tacc0[2][4][4], tacc1[2][4][4];
    #pragma unroll
    for (int mm = 0; mm < 2; mm++)
        #pragma unroll
        for (int nt = 0; nt < 4; nt++)
            #pragma unroll
            for (int j = 0; j < 4; j++) { tacc0[mm][nt][j] = 0.f; tacc1[mm][nt][j] = 0.f; }

    const uint32_t aX_hi  = SB + OFF_X + (uint32_t)((wr * 32 + lrow) * 512);
    const uint32_t aX_lo  = aX_hi + 32768u;
    const uint32_t aH_row = (uint32_t)((wr * 32 + lrow) * 128);
    const uint32_t bW1    = (uint32_t)((wc * 32 + lrow) * 256);
    const uint32_t bW23   = (uint32_t)((wc * 32 + lrow) * 128);

    for (int e = 0; e < 12; e++) {
        const float* b1p = (e < 8) ? bt1 + e * 64 : bs1 + (e - 8) * 64;
        const float* b2p = (e < 8) ? bt2 + e * 64 : bs2 + (e - 8) * 64;
        const float* b3p = (e < 8) ? bt3 + e * 64 : bs3 + (e - 8) * 64;

        float acc[2][4][4];
        #pragma unroll
        for (int mm = 0; mm < 2; mm++)
            #pragma unroll
            for (int nt = 0; nt < 4; nt++)
                #pragma unroll
                for (int j = 0; j < 4; j++) acc[mm][nt][j] = 0.f;

        // ---- layer 1 in two 128-deep K chunks (32KB staging each) ----
        #pragma unroll
        for (int c = 0; c < 2; c++) {
            __syncthreads();   // scratch free (prev phase's reads done)
            {
                const uint4* sH = (const uint4*)(g_W1hi + (e * 2 + c) * 8192);
                const uint4* sL = (const uint4*)(g_W1lo + (e * 2 + c) * 8192);
                #pragma unroll
                for (int i = 0; i < 8; i++) {
                    int j = tid + i * NT;      // 0..1023 uint4
                    ((uint4*)(S + OFF_SCR + SCR_W1HI))[j] = sH[j];
                    ((uint4*)(S + OFF_SCR + SCR_W1LO))[j] = sL[j];
                }
            }
            __syncthreads();
            gemm_warp<8, 512, 256>(aX_hi + c * 256u, aX_lo + c * 256u,
                                   SB + OFF_SCR + SCR_W1HI + bW1,
                                   SB + OFF_SCR + SCR_W1LO + bW1,
                                   row7, khalf, acc);
        }
        __syncthreads();   // W1 reads done; H1 + W2 overwrite scratch

        // ---- epilogue 1 -> H1 [0,16K); stage W2 [16K,32K) ----
        epilogue(acc, b1p, S, OFF_SCR + SCR_H1HI, OFF_SCR + SCR_H1LO, wr, wc, lane);
        {
            const uint4* sH = (const uint4*)(g_W23hi + (e * 2 + 0) * 4096);
            const uint4* sL = (const uint4*)(g_W23lo + (e * 2 + 0) * 4096);
            #pragma unroll
            for (int i = 0; i < 4; i++) {
                int j = tid + i * NT;          // 0..511 uint4
                ((uint4*)(S + OFF_SCR + SCR_W2HI))[j] = sH[j];
                ((uint4*)(S + OFF_SCR + SCR_W2LO))[j] = sL[j];
            }
        }
        __syncthreads();

        // ---- layer 2: [64,64] x [64,64] ----
        #pragma unroll
        for (int mm = 0; mm < 2; mm++)
            #pragma unroll
            for (int nt = 0; nt < 4; nt++)
                #pragma unroll
                for (int j = 0; j < 4; j++) acc[mm][nt][j] = 0.f;
        gemm_warp<4, 128, 128>(SB + OFF_SCR + SCR_H1HI + aH_row,
                               SB + OFF_SCR + SCR_H1LO + aH_row,
                               SB + OFF_SCR + SCR_W2HI + bW23,
                               SB + OFF_SCR + SCR_W2LO + bW23,
                               row7, khalf, acc);
        __syncthreads();   // H1 + W2 reads done

        // ---- epilogue 2 -> H2 (over W2); stage W3 (over H1) ----
        epilogue(acc, b2p, S, OFF_SCR + SCR_H2HI, OFF_SCR + SCR_H2LO, wr, wc, lane);
        {
            const uint4* sH = (const uint4*)(g_W23hi + (e * 2 + 1) * 4096);
            const uint4* sL = (const uint4*)(g_W23lo + (e * 2 + 1) * 4096);
            #pragma unroll
            for (int i = 0; i < 4; i++) {
                int j = tid + i * NT;
                ((uint4*)(S + OFF_SCR + SCR_W3HI))[j] = sH[j];
                ((uint4*)(S + OFF_SCR + SCR_W3LO))[j] = sL[j];
            }
        }
        __syncthreads();

        // ---- layer 3: [64,64] x [64,64] ----
        #pragma unroll
        for (int mm = 0; mm < 2; mm++)
            #pragma unroll
            for (int nt = 0; nt < 4; nt++)
                #pragma unroll
                for (int j = 0; j < 4; j++) acc[mm][nt][j] = 0.f;
        gemm_warp<4, 128, 128>(SB + OFF_SCR + SCR_H2HI + aH_row,
                               SB + OFF_SCR + SCR_H2LO + aH_row,
                               SB + OFF_SCR + SCR_W3HI + bW23,
                               SB + OFF_SCR + SCR_W3LO + bW23,
                               row7, khalf, acc);

        // ---- gated accumulation (next loop-top sync protects scratch) ----
        {
            int g = lane >> 2, t4 = lane & 3;
            #pragma unroll
            for (int mm = 0; mm < 2; mm++) {
                int m0 = wr * 32 + mm * 16 + g, m1 = m0 + 8;
                if (e < 8) {
                    int t = e >> 2;
                    float g0 = sGate[m0 * 16 + t * 8 + (e & 3)];
                    float g1 = sGate[m1 * 16 + t * 8 + (e & 3)];
                    float (*ta)[4][4] = t ? tacc1 : tacc0;
                    #pragma unroll
                    for (int nt = 0; nt < 4; nt++) {
                        int col = wc * 32 + nt * 8 + t4 * 2;
                        float bx = b3p[col], by = b3p[col + 1];
                        ta[mm][nt][0] += g0 * (acc[mm][nt][0] + bx);
                        ta[mm][nt][1] += g0 * (acc[mm][nt][1] + by);
                        ta[mm][nt][2] += g1 * (acc[mm][nt][2] + bx);
                        ta[mm][nt][3] += g1 * (acc[mm][nt][3] + by);
                    }
                } else {
                    int s = e - 8;
                    float g00 = sGate[m0 * 16 + 4 + s],  g01 = sGate[m0 * 16 + 12 + s];
                    float g10 = sGate[m1 * 16 + 4 + s],  g11 = sGate[m1 * 16 + 12 + s];
                    #pragma unroll
                    for (int nt = 0; nt < 4; nt++) {
                        int col = wc * 32 + nt * 8 + t4 * 2;
                        float bx = b3p[col], by = b3p[col + 1];
                        float v0 = acc[mm][nt][0] + bx, v1 = acc[mm][nt][1] + by;
                        float v2 = acc[mm][nt][2] + bx, v3 = acc[mm][nt][3] + by;
                        tacc0[mm][nt][0] += g00 * v0; tacc0[mm][nt][1] += g00 * v1;
                        tacc0[mm][nt][2] += g10 * v2; tacc0[mm][nt][3] += g10 * v3;
                        tacc1[mm][nt][0] += g01 * v0; tacc1[mm][nt][1] += g01 * v1;
                        tacc1[mm][nt][2] += g11 * v2; tacc1[mm][nt][3] += g11 * v3;
                    }
                }
            }
        }
        __syncthreads();   // loop top: scratch free for next expert
    }

    // ---- writeback straight from registers (float2, quad-contiguous) ----
    {
        int g = lane >> 2, t4 = lane & 3;
        #pragma unroll
        for (int mm = 0; mm < 2; mm++) {
            int m0 = bm + wr * 32 + mm * 16 + g, m1 = m0 + 8;
            #pragma unroll
            for (int nt = 0; nt < 4; nt++) {
                int col = wc * 32 + nt * 8 + t4 * 2;
                *(float2*)(Out + (size_t)m0 * 128 + col)      = make_float2(tacc0[mm][nt][0], tacc0[mm][nt][1]);
                *(float2*)(Out + (size_t)m1 * 128 + col)      = make_float2(tacc0[mm][nt][2], tacc0[mm][nt][3]);
                *(float2*)(Out + (size_t)m0 * 128 + 64 + col) = make_float2(tacc1[mm][nt][0], tacc1[mm][nt][1]);
                *(float2*)(Out + (size_t)m1 * 128 + 64 + col) = make_float2(tacc1[mm][nt][2], tacc1[mm][nt][3]);
            }
        }
    }
}

// ===========================================================================
extern "C" void kernel_launch(void* const* d_in, const int* in_sizes, int n_in,
                              void* d_out, int out_size) {
    const float* X   = (const float*)d_in[0];
    const float* Wt1 = (const float*)d_in[1];
    const float* bt1 = (const float*)d_in[2];
    const float* Wt2 = (const float*)d_in[3];
    const float* bt2 = (const float*)d_in[4];
    const float* Wt3 = (const float*)d_in[5];
    const float* bt3 = (const float*)d_in[6];
    const float* Ws1 = (const float*)d_in[7];
    const float* bs1 = (const float*)d_in[8];
    const float* Ws2 = (const float*)d_in[9];
    const float* bs2 = (const float*)d_in[10];
    const float* Ws3 = (const float*)d_in[11];
    const float* bs3 = (const float*)d_in[12];
    const float* Wg  = (const float*)d_in[13];
    const float* bg  = (const float*)d_in[14];
    float* Out = (float*)d_out;

    int B = in_sizes[0] / 256;
    int grid = B / MT;

    prep_w<<<1152, 256>>>(Wt1, Wt2, Wt3, Ws1, Ws2, Ws3);

    cudaFuncSetAttribute((const void*)moe_mma,
                         cudaFuncAttributeMaxDynamicSharedMemorySize, (int)SM_SIZE);
    moe_mma<<<grid, NT, SM_SIZE>>>(X, bt1, bt2, bt3, bs1, bs2, bs3, Wg, bg, Out);
}